// round 1
// baseline (speedup 1.0000x reference)
#include <cuda_runtime.h>

#define N_SITES 100000
#define DIM 128
#define HID 512
#define KVOL 343

// ---------------- scratch (no runtime allocation allowed) ----------------
__device__ float g_xln[(size_t)N_SITES * DIM];   // post-LN activations [N,128]
__device__ float g_h[(size_t)N_SITES * HID];     // post-GELU activations [N,512]
__device__ float g_ssq[HID];                     // per-channel sum of squares
__device__ float g_scale[HID];                   // 1 + grn_g * nx
__device__ float g_c2[DIM];                      // b2 + grn_b @ w2

// ---------------- packed f32x2 helpers (FFMA2 path) ----------------
__device__ __forceinline__ unsigned long long pk2(float lo, float hi) {
    unsigned long long r;
    asm("mov.b64 %0, {%1, %2};" : "=l"(r) : "f"(lo), "f"(hi));
    return r;
}
__device__ __forceinline__ void upk2(unsigned long long v, float& lo, float& hi) {
    asm("mov.b64 {%0, %1}, %2;" : "=f"(lo), "=f"(hi) : "l"(v));
}
__device__ __forceinline__ void fma2(unsigned long long& d, unsigned long long a,
                                     unsigned long long b) {
    asm("fma.rn.f32x2 %0, %1, %2, %0;" : "+l"(d) : "l"(a), "l"(b));
}

__device__ __forceinline__ float gelu_exact(float x) {
    return 0.5f * x * (1.0f + erff(x * 0.7071067811865475f));
}

// ---------------- kernel 0: zero the ssq accumulator ----------------
__global__ void k_zero() {
    int t = threadIdx.x;
    if (t < HID) g_ssq[t] = 0.0f;
}

// ---------------- kernel 1: sparse depthwise conv + LayerNorm ----------------
// One warp per site. Lanes cooperatively scan 343 neighbor indices, ballot out
// the ~9 valid ones, then do float4 gather-FMA over 128 channels (4/lane).
__global__ __launch_bounds__(256) void k_dwln(
    const float* __restrict__ feats, const int* __restrict__ nidx,
    const float* __restrict__ dww, const float* __restrict__ dwb,
    const float* __restrict__ lng, const float* __restrict__ lnb) {
    int warp = (blockIdx.x * blockDim.x + threadIdx.x) >> 5;
    int lane = threadIdx.x & 31;
    if (warp >= N_SITES) return;

    const int* nb = nidx + (size_t)warp * KVOL;
    float4 acc = make_float4(0.f, 0.f, 0.f, 0.f);

    #pragma unroll 1
    for (int base = 0; base < KVOL; base += 32) {
        int k = base + lane;
        int idx = (k < KVOL) ? __ldg(nb + k) : N_SITES;
        unsigned m = __ballot_sync(0xffffffffu, idx < N_SITES);
        while (m) {
            int b = __ffs(m) - 1;
            m &= m - 1;
            int id = __shfl_sync(0xffffffffu, idx, b);
            int kk = base + b;
            float4 f = *(const float4*)(feats + (size_t)id * DIM + lane * 4);
            float4 w = *(const float4*)(dww + (size_t)kk * DIM + lane * 4);
            acc.x = fmaf(f.x, w.x, acc.x);
            acc.y = fmaf(f.y, w.y, acc.y);
            acc.z = fmaf(f.z, w.z, acc.z);
            acc.w = fmaf(f.w, w.w, acc.w);
        }
    }
    float4 bb = *(const float4*)(dwb + lane * 4);
    acc.x += bb.x; acc.y += bb.y; acc.z += bb.z; acc.w += bb.w;

    // LayerNorm over 128 channels (warp holds all of them)
    float s = acc.x + acc.y + acc.z + acc.w;
    float q = acc.x * acc.x + acc.y * acc.y + acc.z * acc.z + acc.w * acc.w;
    #pragma unroll
    for (int o = 16; o; o >>= 1) {
        s += __shfl_xor_sync(0xffffffffu, s, o);
        q += __shfl_xor_sync(0xffffffffu, q, o);
    }
    float mu = s * (1.0f / DIM);
    float var = q * (1.0f / DIM) - mu * mu;
    float rs = rsqrtf(var + 1e-6f);

    float4 g = *(const float4*)(lng + lane * 4);
    float4 be = *(const float4*)(lnb + lane * 4);
    float4 o;
    o.x = (acc.x - mu) * rs * g.x + be.x;
    o.y = (acc.y - mu) * rs * g.y + be.y;
    o.z = (acc.z - mu) * rs * g.z + be.z;
    o.w = (acc.w - mu) * rs * g.w + be.w;
    *(float4*)(g_xln + (size_t)warp * DIM + lane * 4) = o;
}

// ---------------- kernel 2: GEMM1 (xln @ w1) + bias + GELU + ssq ----------------
// Tile: 128 rows x 128 cols, K=128 in 4 chunks of 32. 256 threads, 8x8 micro-tile.
#define BM 128
#define BN 128
#define BK 32
__global__ __launch_bounds__(256, 1) void k_gemm1(const float* __restrict__ w1,
                                                  const float* __restrict__ b1) {
    __shared__ float Xs[BM][BK];   // 16 KB
    __shared__ float Ws[BK][BN];   // 16 KB
    __shared__ float ssqs[BN];

    int tid = threadIdx.x;
    int tx = tid & 15;       // col group
    int ty = tid >> 4;       // row group
    int row0 = blockIdx.x * BM + ty * 8;
    int col0 = blockIdx.y * BN + tx * 8;

    if (tid < BN) ssqs[tid] = 0.0f;

    unsigned long long acc[8][4];
    #pragma unroll
    for (int i = 0; i < 8; i++)
        #pragma unroll
        for (int j = 0; j < 4; j++) acc[i][j] = 0ull;

    for (int kc = 0; kc < DIM / BK; kc++) {
        int k0 = kc * BK;
        // load X tile (zero-pad rows >= N)
        #pragma unroll
        for (int p = 0; p < 4; p++) {
            int lin = p * 256 + tid;
            int q = lin & 7, r = lin >> 3;
            int gr = blockIdx.x * BM + r;
            float4 v = make_float4(0.f, 0.f, 0.f, 0.f);
            if (gr < N_SITES) v = *(const float4*)(g_xln + (size_t)gr * DIM + k0 + q * 4);
            *(float4*)&Xs[r][q * 4] = v;
        }
        // load W tile
        #pragma unroll
        for (int p = 0; p < 4; p++) {
            int lin = p * 256 + tid;
            int c4 = lin & 31, k = lin >> 5;
            *(float4*)&Ws[k][c4 * 4] =
                *(const float4*)(w1 + (size_t)(k0 + k) * HID + blockIdx.y * BN + c4 * 4);
        }
        __syncthreads();

        #pragma unroll
        for (int k4 = 0; k4 < BK / 4; k4++) {
            float4 xv[8];
            #pragma unroll
            for (int i = 0; i < 8; i++) xv[i] = *(const float4*)&Xs[ty * 8 + i][k4 * 4];
            #pragma unroll
            for (int kk = 0; kk < 4; kk++) {
                float4 wa = *(const float4*)&Ws[k4 * 4 + kk][tx * 8];
                float4 wb = *(const float4*)&Ws[k4 * 4 + kk][tx * 8 + 4];
                unsigned long long w0 = pk2(wa.x, wa.y), w1p = pk2(wa.z, wa.w);
                unsigned long long w2p = pk2(wb.x, wb.y), w3p = pk2(wb.z, wb.w);
                #pragma unroll
                for (int i = 0; i < 8; i++) {
                    float x = (kk == 0) ? xv[i].x : (kk == 1) ? xv[i].y
                            : (kk == 2) ? xv[i].z : xv[i].w;
                    unsigned long long xb = pk2(x, x);
                    fma2(acc[i][0], xb, w0);
                    fma2(acc[i][1], xb, w1p);
                    fma2(acc[i][2], xb, w2p);
                    fma2(acc[i][3], xb, w3p);
                }
            }
        }
        __syncthreads();
    }

    // epilogue: +b1, exact GELU, store h, accumulate per-col sum-of-squares
    float b1r[8];
    #pragma unroll
    for (int j = 0; j < 8; j++) b1r[j] = b1[col0 + j];

    float colsum[8];
    #pragma unroll
    for (int j = 0; j < 8; j++) colsum[j] = 0.0f;

    #pragma unroll
    for (int i = 0; i < 8; i++) {
        int gr = row0 + i;
        if (gr >= N_SITES) continue;
        float v[8];
        #pragma unroll
        for (int j = 0; j < 4; j++) upk2(acc[i][j], v[2 * j], v[2 * j + 1]);
        #pragma unroll
        for (int j = 0; j < 8; j++) {
            float gv = gelu_exact(v[j] + b1r[j]);
            v[j] = gv;
            colsum[j] += gv * gv;
        }
        float4* hp = (float4*)(g_h + (size_t)gr * HID + col0);
        hp[0] = make_float4(v[0], v[1], v[2], v[3]);
        hp[1] = make_float4(v[4], v[5], v[6], v[7]);
    }
    #pragma unroll
    for (int j = 0; j < 8; j++) atomicAdd(&ssqs[tx * 8 + j], colsum[j]);
    __syncthreads();
    if (tid < BN) atomicAdd(&g_ssq[blockIdx.y * BN + tid], ssqs[tid]);
}

// ---------------- kernel 3: GRN scalars + folded constant row ----------------
__global__ void k_grn(const float* __restrict__ grn_g, const float* __restrict__ grn_b,
                      const float* __restrict__ w2, const float* __restrict__ b2) {
    __shared__ float sh[HID];
    int t = threadIdx.x;  // 512 threads
    float gx = sqrtf(g_ssq[t]);
    sh[t] = gx;
    __syncthreads();
    for (int o = 256; o; o >>= 1) {
        if (t < o) sh[t] += sh[t + o];
        __syncthreads();
    }
    float mean = sh[0] * (1.0f / HID);
    float nx = gx / (mean + 1e-6f);
    g_scale[t] = 1.0f + grn_g[t] * nx;

    if (t < DIM) {
        float s = b2[t];
        for (int j = 0; j < HID; j++) s = fmaf(grn_b[j], w2[(size_t)j * DIM + t], s);
        g_c2[t] = s;
    }
}

// ---------------- kernel 4: GRN-scale + GEMM2 (h' @ w2) + c2 + residual ----------------
__global__ __launch_bounds__(256, 1) void k_gemm2(const float* __restrict__ w2,
                                                  const float* __restrict__ feats,
                                                  float* __restrict__ out) {
    __shared__ float As[BM][BK];   // 16 KB
    __shared__ float Ws[BK][BN];   // 16 KB  (BN = 128 = full output width)

    int tid = threadIdx.x;
    int tx = tid & 15;
    int ty = tid >> 4;
    int row0 = blockIdx.x * BM + ty * 8;
    int col0 = tx * 8;

    unsigned long long acc[8][4];
    #pragma unroll
    for (int i = 0; i < 8; i++)
        #pragma unroll
        for (int j = 0; j < 4; j++) acc[i][j] = 0ull;

    for (int kc = 0; kc < HID / BK; kc++) {
        int k0 = kc * BK;
        // load A tile = h * scale[k]   (zero-pad rows >= N)
        #pragma unroll
        for (int p = 0; p < 4; p++) {
            int lin = p * 256 + tid;
            int q = lin & 7, r = lin >> 3;
            int gr = blockIdx.x * BM + r;
            float4 v = make_float4(0.f, 0.f, 0.f, 0.f);
            if (gr < N_SITES) {
                v = *(const float4*)(g_h + (size_t)gr * HID + k0 + q * 4);
                float4 sc = *(const float4*)(g_scale + k0 + q * 4);
                v.x *= sc.x; v.y *= sc.y; v.z *= sc.z; v.w *= sc.w;
            }
            *(float4*)&As[r][q * 4] = v;
        }
        // load W tile
        #pragma unroll
        for (int p = 0; p < 4; p++) {
            int lin = p * 256 + tid;
            int c4 = lin & 31, k = lin >> 5;
            *(float4*)&Ws[k][c4 * 4] =
                *(const float4*)(w2 + (size_t)(k0 + k) * DIM + c4 * 4);
        }
        __syncthreads();

        #pragma unroll
        for (int k4 = 0; k4 < BK / 4; k4++) {
            float4 xv[8];
            #pragma unroll
            for (int i = 0; i < 8; i++) xv[i] = *(const float4*)&As[ty * 8 + i][k4 * 4];
            #pragma unroll
            for (int kk = 0; kk < 4; kk++) {
                float4 wa = *(const float4*)&Ws[k4 * 4 + kk][tx * 8];
                float4 wb = *(const float4*)&Ws[k4 * 4 + kk][tx * 8 + 4];
                unsigned long long w0 = pk2(wa.x, wa.y), w1p = pk2(wa.z, wa.w);
                unsigned long long w2p = pk2(wb.x, wb.y), w3p = pk2(wb.z, wb.w);
                #pragma unroll
                for (int i = 0; i < 8; i++) {
                    float x = (kk == 0) ? xv[i].x : (kk == 1) ? xv[i].y
                            : (kk == 2) ? xv[i].z : xv[i].w;
                    unsigned long long xb = pk2(x, x);
                    fma2(acc[i][0], xb, w0);
                    fma2(acc[i][1], xb, w1p);
                    fma2(acc[i][2], xb, w2p);
                    fma2(acc[i][3], xb, w3p);
                }
            }
        }
        __syncthreads();
    }

    // epilogue: + c2 + feats residual
    float c2r[8];
    #pragma unroll
    for (int j = 0; j < 8; j++) c2r[j] = g_c2[col0 + j];

    #pragma unroll
    for (int i = 0; i < 8; i++) {
        int gr = row0 + i;
        if (gr >= N_SITES) continue;
        float v[8];
        #pragma unroll
        for (int j = 0; j < 4; j++) upk2(acc[i][j], v[2 * j], v[2 * j + 1]);
        const float4* fp = (const float4*)(feats + (size_t)gr * DIM + col0);
        float4 f0 = fp[0], f1 = fp[1];
        float4 o0 = make_float4(v[0] + c2r[0] + f0.x, v[1] + c2r[1] + f0.y,
                                v[2] + c2r[2] + f0.z, v[3] + c2r[3] + f0.w);
        float4 o1 = make_float4(v[4] + c2r[4] + f1.x, v[5] + c2r[5] + f1.y,
                                v[6] + c2r[6] + f1.z, v[7] + c2r[7] + f1.w);
        float4* op = (float4*)(out + (size_t)gr * DIM + col0);
        op[0] = o0;
        op[1] = o1;
    }
}

// ---------------- launch ----------------
extern "C" void kernel_launch(void* const* d_in, const int* in_sizes, int n_in,
                              void* d_out, int out_size) {
    const float* feats = (const float*)d_in[0];
    const int*   nidx  = (const int*)d_in[1];
    const float* dww   = (const float*)d_in[2];
    const float* dwb   = (const float*)d_in[3];
    const float* lng   = (const float*)d_in[4];
    const float* lnb   = (const float*)d_in[5];
    const float* w1    = (const float*)d_in[6];
    const float* b1    = (const float*)d_in[7];
    const float* grng  = (const float*)d_in[8];
    const float* grnb  = (const float*)d_in[9];
    const float* w2    = (const float*)d_in[10];
    const float* b2    = (const float*)d_in[11];
    float* out = (float*)d_out;

    k_zero<<<1, 512>>>();
    k_dwln<<<(N_SITES * 32 + 255) / 256, 256>>>(feats, nidx, dww, dwb, lng, lnb);
    dim3 g2((N_SITES + BM - 1) / BM, HID / BN);
    k_gemm1<<<g2, 256>>>(w1, b1);
    k_grn<<<1, 512>>>(grng, grnb, w2, b2);
    k_gemm2<<<(N_SITES + BM - 1) / BM, 256>>>(w2, feats, out);
}

// round 3
// speedup vs baseline: 1.1031x; 1.1031x over previous
#include <cuda_runtime.h>
#include <cuda_bf16.h>
#include <cstdint>

#define N_SITES 100000
#define DIM 128
#define HID 512
#define KVOL 343

// ---------------- scratch ----------------
__device__ uint32_t g_xlnp[(size_t)N_SITES * DIM];  // post-LN, packed (bf16 hi<<16 | bf16 lo)
__device__ uint32_t g_hp[(size_t)N_SITES * HID];    // post-GELU, packed
__device__ float g_ssq[HID];
__device__ float g_scale[HID];                      // 1 + grn_g * nx
__device__ float g_c2[DIM];                         // b2 + grn_b @ w2

// ---------------- helpers ----------------
__device__ __forceinline__ uint32_t pack_hilo(float x) {
    __nv_bfloat16 h = __float2bfloat16(x);
    float hf = __bfloat162float(h);
    __nv_bfloat16 l = __float2bfloat16(x - hf);
    return ((uint32_t)__bfloat16_as_ushort(h) << 16) | (uint32_t)__bfloat16_as_ushort(l);
}

__device__ __forceinline__ float gelu_exact(float x) {
    return 0.5f * x * (1.0f + erff(x * 0.7071067811865475f));
}

__device__ __forceinline__ void ldsm4(uint32_t r[4], const void* p) {
    uint32_t a = (uint32_t)__cvta_generic_to_shared(p);
    asm volatile("ldmatrix.sync.aligned.m8n8.x4.shared.b16 {%0,%1,%2,%3}, [%4];"
                 : "=r"(r[0]), "=r"(r[1]), "=r"(r[2]), "=r"(r[3]) : "r"(a));
}
__device__ __forceinline__ void ldsm4t(uint32_t r[4], const void* p) {
    uint32_t a = (uint32_t)__cvta_generic_to_shared(p);
    asm volatile("ldmatrix.sync.aligned.m8n8.x4.trans.shared.b16 {%0,%1,%2,%3}, [%4];"
                 : "=r"(r[0]), "=r"(r[1]), "=r"(r[2]), "=r"(r[3]) : "r"(a));
}
__device__ __forceinline__ void mma16816(float c[4], const uint32_t a[4],
                                         uint32_t b0, uint32_t b1) {
    asm volatile(
        "mma.sync.aligned.m16n8k16.row.col.f32.bf16.bf16.f32 "
        "{%0,%1,%2,%3},{%4,%5,%6,%7},{%8,%9},{%0,%1,%2,%3};"
        : "+f"(c[0]), "+f"(c[1]), "+f"(c[2]), "+f"(c[3])
        : "r"(a[0]), "r"(a[1]), "r"(a[2]), "r"(a[3]), "r"(b0), "r"(b1));
}

// split a float into bf16 hi/lo bit patterns
__device__ __forceinline__ void split_hl(float f, uint16_t& h, uint16_t& l) {
    __nv_bfloat16 hb = __float2bfloat16(f);
    h = __bfloat16_as_ushort(hb);
    l = __bfloat16_as_ushort(__float2bfloat16(f - __bfloat162float(hb)));
}

// ---------------- kernel 0: zero ssq ----------------
__global__ void k_zero() {
    if (threadIdx.x < HID) g_ssq[threadIdx.x] = 0.0f;
}

// ---------------- kernel: c2 = b2 + grn_b @ w2 (input-only, launched early) ----------------
__global__ void k_c2(const float* __restrict__ grn_b, const float* __restrict__ w2,
                     const float* __restrict__ b2) {
    __shared__ float part[4][DIM];
    int t = threadIdx.x;  // 512
    int jg = t >> 7, col = t & 127;
    float s = 0.f;
    #pragma unroll 4
    for (int j = jg * 128; j < jg * 128 + 128; j++)
        s = fmaf(grn_b[j], w2[(size_t)j * DIM + col], s);
    part[jg][col] = s;
    __syncthreads();
    if (t < DIM) g_c2[t] = b2[t] + part[0][t] + part[1][t] + part[2][t] + part[3][t];
}

// ---------------- kernel 1: sparse depthwise conv + LayerNorm -> packed bf16 hi/lo ----------------
__global__ __launch_bounds__(256) void k_dwln(
    const float* __restrict__ feats, const int* __restrict__ nidx,
    const float* __restrict__ dww, const float* __restrict__ dwb,
    const float* __restrict__ lng, const float* __restrict__ lnb) {
    int warp = (blockIdx.x * blockDim.x + threadIdx.x) >> 5;
    int lane = threadIdx.x & 31;
    if (warp >= N_SITES) return;

    const int* nb = nidx + (size_t)warp * KVOL;
    float4 acc = make_float4(0.f, 0.f, 0.f, 0.f);

    #pragma unroll 1
    for (int base = 0; base < KVOL; base += 32) {
        int k = base + lane;
        int idx = (k < KVOL) ? __ldg(nb + k) : N_SITES;
        unsigned m = __ballot_sync(0xffffffffu, idx < N_SITES);
        while (m) {
            int b = __ffs(m) - 1;
            m &= m - 1;
            int id = __shfl_sync(0xffffffffu, idx, b);
            int kk = base + b;
            float4 f = *(const float4*)(feats + (size_t)id * DIM + lane * 4);
            float4 w = *(const float4*)(dww + (size_t)kk * DIM + lane * 4);
            acc.x = fmaf(f.x, w.x, acc.x);
            acc.y = fmaf(f.y, w.y, acc.y);
            acc.z = fmaf(f.z, w.z, acc.z);
            acc.w = fmaf(f.w, w.w, acc.w);
        }
    }
    float4 bb = *(const float4*)(dwb + lane * 4);
    acc.x += bb.x; acc.y += bb.y; acc.z += bb.z; acc.w += bb.w;

    float s = acc.x + acc.y + acc.z + acc.w;
    float q = acc.x * acc.x + acc.y * acc.y + acc.z * acc.z + acc.w * acc.w;
    #pragma unroll
    for (int o = 16; o; o >>= 1) {
        s += __shfl_xor_sync(0xffffffffu, s, o);
        q += __shfl_xor_sync(0xffffffffu, q, o);
    }
    float mu = s * (1.0f / DIM);
    float var = q * (1.0f / DIM) - mu * mu;
    float rs = rsqrtf(var + 1e-6f);

    float4 g = *(const float4*)(lng + lane * 4);
    float4 be = *(const float4*)(lnb + lane * 4);
    float4 o;
    o.x = (acc.x - mu) * rs * g.x + be.x;
    o.y = (acc.y - mu) * rs * g.y + be.y;
    o.z = (acc.z - mu) * rs * g.z + be.z;
    o.w = (acc.w - mu) * rs * g.w + be.w;
    uint4 pk = make_uint4(pack_hilo(o.x), pack_hilo(o.y), pack_hilo(o.z), pack_hilo(o.w));
    *(uint4*)(g_xlnp + (size_t)warp * DIM + lane * 4) = pk;
}

// ---------------- GEMM tiles: 128(M) x 128(N), BK=32, 256 threads, mma.sync bf16 hi/lo ----------------
#define BK 32
#define APAD 8
#define BPAD 8

// GEMM1: g_xlnp[N,128] @ w1[128,512] -> +b1, GELU, store g_hp, accumulate ssq
__global__ __launch_bounds__(256) void k_gemm1(const float* __restrict__ w1,
                                               const float* __restrict__ b1) {
    __shared__ unsigned short As_hi[128][BK + APAD];
    __shared__ unsigned short As_lo[128][BK + APAD];
    __shared__ unsigned short Bs_hi[BK][128 + BPAD];
    __shared__ unsigned short Bs_lo[BK][128 + BPAD];
    __shared__ float ssqs[128];

    int tid = threadIdx.x;
    int lane = tid & 31;
    int wid = tid >> 5;
    int mw = wid & 3;        // 4 M-warps (32 rows each)
    int nw = wid >> 2;       // 2 N-warps (64 cols each)
    int m0 = blockIdx.x * 128;
    int nblk = blockIdx.y;   // 128-col strip of HID

    if (tid < 128) ssqs[tid] = 0.0f;

    float acc[2][8][4];
    #pragma unroll
    for (int i = 0; i < 2; i++)
        #pragma unroll
        for (int j = 0; j < 8; j++)
            #pragma unroll
            for (int r = 0; r < 4; r++) acc[i][j][r] = 0.f;

    for (int kt = 0; kt < DIM / BK; kt++) {
        // --- load A tile (packed u32 -> hi/lo planes) ---
        #pragma unroll
        for (int p = 0; p < 4; p++) {
            int lin = p * 256 + tid;
            int row = lin >> 3, kg = lin & 7;
            uint4 v = make_uint4(0, 0, 0, 0);
            int gr = m0 + row;
            if (gr < N_SITES)
                v = *(const uint4*)(g_xlnp + (size_t)gr * DIM + kt * BK + kg * 4);
            uint32_t h01 = (v.x >> 16) | (v.y & 0xFFFF0000u);
            uint32_t h23 = (v.z >> 16) | (v.w & 0xFFFF0000u);
            uint32_t l01 = (v.x & 0xFFFFu) | (v.y << 16);
            uint32_t l23 = (v.z & 0xFFFFu) | (v.w << 16);
            *(uint2*)&As_hi[row][kg * 4] = make_uint2(h01, h23);
            *(uint2*)&As_lo[row][kg * 4] = make_uint2(l01, l23);
        }
        // --- load B tile (fp32 -> hi/lo planes) ---
        #pragma unroll
        for (int p = 0; p < 4; p++) {
            int lin = p * 256 + tid;
            int k = lin >> 5, ng = lin & 31;
            float4 f = *(const float4*)(w1 + (size_t)(kt * BK + k) * HID + nblk * 128 + ng * 4);
            uint16_t h0, l0, h1, l1, h2, l2, h3, l3;
            split_hl(f.x, h0, l0); split_hl(f.y, h1, l1);
            split_hl(f.z, h2, l2); split_hl(f.w, h3, l3);
            *(uint2*)&Bs_hi[k][ng * 4] =
                make_uint2((uint32_t)h0 | ((uint32_t)h1 << 16), (uint32_t)h2 | ((uint32_t)h3 << 16));
            *(uint2*)&Bs_lo[k][ng * 4] =
                make_uint2((uint32_t)l0 | ((uint32_t)l1 << 16), (uint32_t)l2 | ((uint32_t)l3 << 16));
        }
        __syncthreads();

        #pragma unroll
        for (int ks = 0; ks < BK / 16; ks++) {
            uint32_t ah[2][4], al[2][4];
            #pragma unroll
            for (int mf = 0; mf < 2; mf++) {
                const unsigned short* pa =
                    &As_hi[mw * 32 + mf * 16 + (lane & 15)][ks * 16 + 8 * (lane >> 4)];
                ldsm4(ah[mf], pa);
                const unsigned short* pal =
                    &As_lo[mw * 32 + mf * 16 + (lane & 15)][ks * 16 + 8 * (lane >> 4)];
                ldsm4(al[mf], pal);
            }
            #pragma unroll
            for (int ng = 0; ng < 4; ng++) {
                uint32_t bh[4], bl[4];
                const unsigned short* pb =
                    &Bs_hi[ks * 16 + (lane & 15)][nw * 64 + ng * 16 + 8 * (lane >> 4)];
                ldsm4t(bh, pb);
                const unsigned short* pbl =
                    &Bs_lo[ks * 16 + (lane & 15)][nw * 64 + ng * 16 + 8 * (lane >> 4)];
                ldsm4t(bl, pbl);
                #pragma unroll
                for (int mf = 0; mf < 2; mf++) {
                    mma16816(acc[mf][ng * 2], ah[mf], bh[0], bh[1]);
                    mma16816(acc[mf][ng * 2], ah[mf], bl[0], bl[1]);
                    mma16816(acc[mf][ng * 2], al[mf], bh[0], bh[1]);
                    mma16816(acc[mf][ng * 2 + 1], ah[mf], bh[2], bh[3]);
                    mma16816(acc[mf][ng * 2 + 1], ah[mf], bl[2], bl[3]);
                    mma16816(acc[mf][ng * 2 + 1], al[mf], bh[2], bh[3]);
                }
            }
        }
        __syncthreads();
    }

    // --- epilogue: +b1, GELU, pack-store h, ssq ---
    int colb = nblk * 128 + nw * 64 + (lane & 3) * 2;  // global col base; +nf*8
    float b1v[8][2];
    #pragma unroll
    for (int nf = 0; nf < 8; nf++) {
        b1v[nf][0] = b1[colb + nf * 8];
        b1v[nf][1] = b1[colb + nf * 8 + 1];
    }
    float ss[16];
    #pragma unroll
    for (int i = 0; i < 16; i++) ss[i] = 0.f;

    #pragma unroll
    for (int mf = 0; mf < 2; mf++) {
        #pragma unroll
        for (int half = 0; half < 2; half++) {
            int r = m0 + mw * 32 + mf * 16 + (lane >> 2) + half * 8;
            if (r >= N_SITES) continue;
            uint32_t* hrow = g_hp + (size_t)r * HID;
            #pragma unroll
            for (int nf = 0; nf < 8; nf++) {
                float v0 = gelu_exact(acc[mf][nf][half * 2] + b1v[nf][0]);
                float v1 = gelu_exact(acc[mf][nf][half * 2 + 1] + b1v[nf][1]);
                ss[nf * 2] += v0 * v0;
                ss[nf * 2 + 1] += v1 * v1;
                *(uint2*)(hrow + colb + nf * 8) = make_uint2(pack_hilo(v0), pack_hilo(v1));
            }
        }
    }
    __syncthreads();  // ssqs zero-init visible (also loop syncs) & acc done
    int lcolb = nw * 64 + (lane & 3) * 2;
    #pragma unroll
    for (int nf = 0; nf < 8; nf++) {
        atomicAdd(&ssqs[lcolb + nf * 8], ss[nf * 2]);
        atomicAdd(&ssqs[lcolb + nf * 8 + 1], ss[nf * 2 + 1]);
    }
    __syncthreads();
    if (tid < 128) atomicAdd(&g_ssq[nblk * 128 + tid], ssqs[tid]);
}

// ---------------- kernel: GRN scale ----------------
__global__ void k_grn(const float* __restrict__ grn_g) {
    __shared__ float sh[HID];
    int t = threadIdx.x;  // 512
    float gx = sqrtf(g_ssq[t]);
    sh[t] = gx;
    __syncthreads();
    for (int o = 256; o; o >>= 1) {
        if (t < o) sh[t] += sh[t + o];
        __syncthreads();
    }
    float nx = gx / (sh[0] * (1.0f / HID) + 1e-6f);
    g_scale[t] = 1.0f + grn_g[t] * nx;
}

// GEMM2: (g_hp * scale)[N,512] @ w2[512,128] -> + c2 + feats -> out
__global__ __launch_bounds__(256) void k_gemm2(const float* __restrict__ w2,
                                               const float* __restrict__ feats,
                                               float* __restrict__ out) {
    __shared__ unsigned short As_hi[128][BK + APAD];
    __shared__ unsigned short As_lo[128][BK + APAD];
    __shared__ unsigned short Bs_hi[BK][128 + BPAD];
    __shared__ unsigned short Bs_lo[BK][128 + BPAD];

    int tid = threadIdx.x;
    int lane = tid & 31;
    int wid = tid >> 5;
    int mw = wid & 3;
    int nw = wid >> 2;
    int m0 = blockIdx.x * 128;

    float acc[2][8][4];
    #pragma unroll
    for (int i = 0; i < 2; i++)
        #pragma unroll
        for (int j = 0; j < 8; j++)
            #pragma unroll
            for (int r = 0; r < 4; r++) acc[i][j][r] = 0.f;

    for (int kt = 0; kt < HID / BK; kt++) {
        #pragma unroll
        for (int p = 0; p < 4; p++) {
            int lin = p * 256 + tid;
            int row = lin >> 3, kg = lin & 7;
            uint4 v = make_uint4(0, 0, 0, 0);
            int gr = m0 + row;
            if (gr < N_SITES)
                v = *(const uint4*)(g_hp + (size_t)gr * HID + kt * BK + kg * 4);
            uint32_t h01 = (v.x >> 16) | (v.y & 0xFFFF0000u);
            uint32_t h23 = (v.z >> 16) | (v.w & 0xFFFF0000u);
            uint32_t l01 = (v.x & 0xFFFFu) | (v.y << 16);
            uint32_t l23 = (v.z & 0xFFFFu) | (v.w << 16);
            *(uint2*)&As_hi[row][kg * 4] = make_uint2(h01, h23);
            *(uint2*)&As_lo[row][kg * 4] = make_uint2(l01, l23);
        }
        // B = w2 row-scaled by g_scale[k] (GRN fold)
        #pragma unroll
        for (int p = 0; p < 4; p++) {
            int lin = p * 256 + tid;
            int k = lin >> 5, ng = lin & 31;
            float sc = g_scale[kt * BK + k];
            float4 f = *(const float4*)(w2 + (size_t)(kt * BK + k) * DIM + ng * 4);
            f.x *= sc; f.y *= sc; f.z *= sc; f.w *= sc;
            uint16_t h0, l0, h1, l1, h2, l2, h3, l3;
            split_hl(f.x, h0, l0); split_hl(f.y, h1, l1);
            split_hl(f.z, h2, l2); split_hl(f.w, h3, l3);
            *(uint2*)&Bs_hi[k][ng * 4] =
                make_uint2((uint32_t)h0 | ((uint32_t)h1 << 16), (uint32_t)h2 | ((uint32_t)h3 << 16));
            *(uint2*)&Bs_lo[k][ng * 4] =
                make_uint2((uint32_t)l0 | ((uint32_t)l1 << 16), (uint32_t)l2 | ((uint32_t)l3 << 16));
        }
        __syncthreads();

        #pragma unroll
        for (int ks = 0; ks < BK / 16; ks++) {
            uint32_t ah[2][4], al[2][4];
            #pragma unroll
            for (int mf = 0; mf < 2; mf++) {
                const unsigned short* pa =
                    &As_hi[mw * 32 + mf * 16 + (lane & 15)][ks * 16 + 8 * (lane >> 4)];
                ldsm4(ah[mf], pa);
                const unsigned short* pal =
                    &As_lo[mw * 32 + mf * 16 + (lane & 15)][ks * 16 + 8 * (lane >> 4)];
                ldsm4(al[mf], pal);
            }
            #pragma unroll
            for (int ng = 0; ng < 4; ng++) {
                uint32_t bh[4], bl[4];
                const unsigned short* pb =
                    &Bs_hi[ks * 16 + (lane & 15)][nw * 64 + ng * 16 + 8 * (lane >> 4)];
                ldsm4t(bh, pb);
                const unsigned short* pbl =
                    &Bs_lo[ks * 16 + (lane & 15)][nw * 64 + ng * 16 + 8 * (lane >> 4)];
                ldsm4t(bl, pbl);
                #pragma unroll
                for (int mf = 0; mf < 2; mf++) {
                    mma16816(acc[mf][ng * 2], ah[mf], bh[0], bh[1]);
                    mma16816(acc[mf][ng * 2], ah[mf], bl[0], bl[1]);
                    mma16816(acc[mf][ng * 2], al[mf], bh[0], bh[1]);
                    mma16816(acc[mf][ng * 2 + 1], ah[mf], bh[2], bh[3]);
                    mma16816(acc[mf][ng * 2 + 1], ah[mf], bl[2], bl[3]);
                    mma16816(acc[mf][ng * 2 + 1], al[mf], bh[2], bh[3]);
                }
            }
        }
        __syncthreads();
    }

    // --- epilogue: + c2 + residual ---
    int colb = nw * 64 + (lane & 3) * 2;
    float c2v[8][2];
    #pragma unroll
    for (int nf = 0; nf < 8; nf++) {
        c2v[nf][0] = g_c2[colb + nf * 8];
        c2v[nf][1] = g_c2[colb + nf * 8 + 1];
    }
    #pragma unroll
    for (int mf = 0; mf < 2; mf++) {
        #pragma unroll
        for (int half = 0; half < 2; half++) {
            int r = m0 + mw * 32 + mf * 16 + (lane >> 2) + half * 8;
            if (r >= N_SITES) continue;
            const float* frow = feats + (size_t)r * DIM;
            float* orow = out + (size_t)r * DIM;
            #pragma unroll
            for (int nf = 0; nf < 8; nf++) {
                float2 fv = *(const float2*)(frow + colb + nf * 8);
                float2 ov;
                ov.x = acc[mf][nf][half * 2] + c2v[nf][0] + fv.x;
                ov.y = acc[mf][nf][half * 2 + 1] + c2v[nf][1] + fv.y;
                *(float2*)(orow + colb + nf * 8) = ov;
            }
        }
    }
}

// ---------------- launch ----------------
extern "C" void kernel_launch(void* const* d_in, const int* in_sizes, int n_in,
                              void* d_out, int out_size) {
    const float* feats = (const float*)d_in[0];
    const int*   nidx  = (const int*)d_in[1];
    const float* dww   = (const float*)d_in[2];
    const float* dwb   = (const float*)d_in[3];
    const float* lng   = (const float*)d_in[4];
    const float* lnb   = (const float*)d_in[5];
    const float* w1    = (const float*)d_in[6];
    const float* b1    = (const float*)d_in[7];
    const float* grng  = (const float*)d_in[8];
    const float* grnb  = (const float*)d_in[9];
    const float* w2    = (const float*)d_in[10];
    const float* b2    = (const float*)d_in[11];
    float* out = (float*)d_out;

    k_zero<<<1, 512>>>();
    k_c2<<<1, 512>>>(grnb, w2, b2);
    k_dwln<<<(N_SITES * 32 + 255) / 256, 256>>>(feats, nidx, dww, dwb, lng, lnb);
    dim3 g1((N_SITES + 127) / 128, HID / 128);
    k_gemm1<<<g1, 256>>>(w1, b1);
    k_grn<<<1, 512>>>(grng);
    k_gemm2<<<(N_SITES + 127) / 128, 256>>>(w2, feats, out);
}

// round 5
// speedup vs baseline: 1.6546x; 1.4999x over previous
#include <cuda_runtime.h>
#include <cuda_bf16.h>
#include <cstdint>

#define N_SITES 100000
#define DIM 128
#define HID 512
#define KVOL 343

typedef unsigned short u16;
typedef unsigned int u32;

// ---------------- scratch (hi/lo bf16 planes) ----------------
__device__ __align__(16) u16 g_xh[(size_t)N_SITES * DIM];
__device__ __align__(16) u16 g_xl[(size_t)N_SITES * DIM];
__device__ __align__(16) u16 g_hh[(size_t)N_SITES * HID];
__device__ __align__(16) u16 g_hl[(size_t)N_SITES * HID];
__device__ __align__(16) u16 g_w1h[DIM * HID];
__device__ __align__(16) u16 g_w1l[DIM * HID];
__device__ __align__(16) u16 g_w2h[HID * DIM];
__device__ __align__(16) u16 g_w2l[HID * DIM];
__device__ float g_ssq[HID];
__device__ float g_scale[HID];
__device__ float g_c2[DIM];

// ---------------- helpers ----------------
__device__ __forceinline__ void split_hl(float f, u16& h, u16& l) {
    __nv_bfloat16 hb = __float2bfloat16(f);
    h = __bfloat16_as_ushort(hb);
    l = __bfloat16_as_ushort(__float2bfloat16(f - __bfloat162float(hb)));
}
__device__ __forceinline__ float gelu_exact(float x) {
    return 0.5f * x * (1.0f + erff(x * 0.7071067811865475f));
}
__device__ __forceinline__ void ldsm4(uint32_t r[4], const void* p) {
    uint32_t a = (uint32_t)__cvta_generic_to_shared(p);
    asm volatile("ldmatrix.sync.aligned.m8n8.x4.shared.b16 {%0,%1,%2,%3}, [%4];"
                 : "=r"(r[0]), "=r"(r[1]), "=r"(r[2]), "=r"(r[3]) : "r"(a));
}
__device__ __forceinline__ void ldsm4t(uint32_t r[4], const void* p) {
    uint32_t a = (uint32_t)__cvta_generic_to_shared(p);
    asm volatile("ldmatrix.sync.aligned.m8n8.x4.trans.shared.b16 {%0,%1,%2,%3}, [%4];"
                 : "=r"(r[0]), "=r"(r[1]), "=r"(r[2]), "=r"(r[3]) : "r"(a));
}
__device__ __forceinline__ void mma16816(float c[4], const uint32_t a[4],
                                         uint32_t b0, uint32_t b1) {
    asm volatile(
        "mma.sync.aligned.m16n8k16.row.col.f32.bf16.bf16.f32 "
        "{%0,%1,%2,%3},{%4,%5,%6,%7},{%8,%9},{%0,%1,%2,%3};"
        : "+f"(c[0]), "+f"(c[1]), "+f"(c[2]), "+f"(c[3])
        : "r"(a[0]), "r"(a[1]), "r"(a[2]), "r"(a[3]), "r"(b0), "r"(b1));
}
__device__ __forceinline__ void cpa16(u16* dst, const u16* src, bool valid) {
    uint32_t d = (uint32_t)__cvta_generic_to_shared(dst);
    int sz = valid ? 16 : 0;
    asm volatile("cp.async.cg.shared.global [%0], [%1], 16, %2;\n"
                 :: "r"(d), "l"(src), "r"(sz));
}
__device__ __forceinline__ void cpa_commit() {
    asm volatile("cp.async.commit_group;\n");
}

// ---------------- init: zero ssq + c2 = b2 + grn_b @ w2 ----------------
__global__ void k_init(const float* __restrict__ grn_b, const float* __restrict__ w2,
                       const float* __restrict__ b2) {
    __shared__ float part[4][DIM];
    int t = threadIdx.x;  // 512
    g_ssq[t] = 0.0f;
    int jg = t >> 7, col = t & 127;
    float s = 0.f;
    #pragma unroll 4
    for (int j = jg * 128; j < jg * 128 + 128; j++)
        s = fmaf(grn_b[j], w2[(size_t)j * DIM + col], s);
    part[jg][col] = s;
    __syncthreads();
    if (t < DIM) g_c2[t] = b2[t] + part[0][t] + part[1][t] + part[2][t] + part[3][t];
}

// ---------------- prep: split w1 into hi/lo planes ----------------
__global__ void k_w1prep(const float* __restrict__ w1) {
    int idx = blockIdx.x * 512 + threadIdx.x;  // grid 128 x 512
    float f = w1[idx];
    u16 h, l;
    split_hl(f, h, l);
    g_w1h[idx] = h;
    g_w1l[idx] = l;
}

// ---------------- prep: split (scale[k] * w2) into hi/lo planes ----------------
__global__ void k_w2prep(const float* __restrict__ w2) {
    int idx = blockIdx.x * 512 + threadIdx.x;  // grid 128 x 512
    int k = idx >> 7;
    float f = g_scale[k] * w2[idx];
    u16 h, l;
    split_hl(f, h, l);
    g_w2h[idx] = h;
    g_w2l[idx] = l;
}

// ---------------- kernel 1: sparse depthwise conv + LayerNorm -> hi/lo planes ----------------
__global__ __launch_bounds__(256) void k_dwln(
    const float* __restrict__ feats, const int* __restrict__ nidx,
    const float* __restrict__ dww, const float* __restrict__ dwb,
    const float* __restrict__ lng, const float* __restrict__ lnb) {
    int warp = (blockIdx.x * blockDim.x + threadIdx.x) >> 5;
    int lane = threadIdx.x & 31;
    if (warp >= N_SITES) return;

    const int* nb = nidx + (size_t)warp * KVOL;
    float4 acc = make_float4(0.f, 0.f, 0.f, 0.f);

    #pragma unroll 1
    for (int base = 0; base < KVOL; base += 32) {
        int k = base + lane;
        int idx = (k < KVOL) ? __ldg(nb + k) : N_SITES;
        unsigned m = __ballot_sync(0xffffffffu, idx < N_SITES);
        while (m) {
            int b = __ffs(m) - 1;
            m &= m - 1;
            int id = __shfl_sync(0xffffffffu, idx, b);
            int kk = base + b;
            float4 f = *(const float4*)(feats + (size_t)id * DIM + lane * 4);
            float4 w = *(const float4*)(dww + (size_t)kk * DIM + lane * 4);
            acc.x = fmaf(f.x, w.x, acc.x);
            acc.y = fmaf(f.y, w.y, acc.y);
            acc.z = fmaf(f.z, w.z, acc.z);
            acc.w = fmaf(f.w, w.w, acc.w);
        }
    }
    float4 bb = *(const float4*)(dwb + lane * 4);
    acc.x += bb.x; acc.y += bb.y; acc.z += bb.z; acc.w += bb.w;

    float s = acc.x + acc.y + acc.z + acc.w;
    float q = acc.x * acc.x + acc.y * acc.y + acc.z * acc.z + acc.w * acc.w;
    #pragma unroll
    for (int o = 16; o; o >>= 1) {
        s += __shfl_xor_sync(0xffffffffu, s, o);
        q += __shfl_xor_sync(0xffffffffu, q, o);
    }
    float mu = s * (1.0f / DIM);
    float var = q * (1.0f / DIM) - mu * mu;
    float rs = rsqrtf(var + 1e-6f);

    float4 g = *(const float4*)(lng + lane * 4);
    float4 be = *(const float4*)(lnb + lane * 4);
    float o0 = (acc.x - mu) * rs * g.x + be.x;
    float o1 = (acc.y - mu) * rs * g.y + be.y;
    float o2 = (acc.z - mu) * rs * g.z + be.z;
    float o3 = (acc.w - mu) * rs * g.w + be.w;
    u16 h0, l0, h1, l1, h2, l2, h3, l3;
    split_hl(o0, h0, l0); split_hl(o1, h1, l1);
    split_hl(o2, h2, l2); split_hl(o3, h3, l3);
    size_t off = (size_t)warp * DIM + lane * 4;
    *(uint2*)(g_xh + off) = make_uint2((u32)h0 | ((u32)h1 << 16), (u32)h2 | ((u32)h3 << 16));
    *(uint2*)(g_xl + off) = make_uint2((u32)l0 | ((u32)l1 << 16), (u32)l2 | ((u32)l3 << 16));
}

// ---------------- GEMM common: 128x128 tile, BK=32, 256 thr, 2-stage cp.async ----------------
// smem layout (u16 units per stage): A_hi@0 (128x40), A_lo@5120, B_hi@10240 (32x136), B_lo@14592
#define SM_ALO 5120
#define SM_BHI 10240
#define SM_BLO 14592
#define SM_STAGE 18944
#define SMEM_BYTES (2 * SM_STAGE * 2)

__device__ __forceinline__ void mma_tile(const u16* base, int lane, int mw, int nw,
                                         float acc[2][8][4]) {
    #pragma unroll
    for (int ks = 0; ks < 2; ks++) {
        uint32_t ah[2][4], al[2][4];
        #pragma unroll
        for (int mf = 0; mf < 2; mf++) {
            int arow = mw * 32 + mf * 16 + (lane & 15);
            int acol = ks * 16 + 8 * (lane >> 4);
            ldsm4(ah[mf], base + arow * 40 + acol);
            ldsm4(al[mf], base + SM_ALO + arow * 40 + acol);
        }
        #pragma unroll
        for (int ng = 0; ng < 4; ng++) {
            uint32_t bh[4], bl[4];
            int brow = ks * 16 + (lane & 15);
            int bcol = nw * 64 + ng * 16 + 8 * (lane >> 4);
            ldsm4t(bh, base + SM_BHI + brow * 136 + bcol);
            ldsm4t(bl, base + SM_BLO + brow * 136 + bcol);
            #pragma unroll
            for (int mf = 0; mf < 2; mf++) {
                mma16816(acc[mf][ng * 2], ah[mf], bh[0], bh[1]);
                mma16816(acc[mf][ng * 2], ah[mf], bl[0], bl[1]);
                mma16816(acc[mf][ng * 2], al[mf], bh[0], bh[1]);
                mma16816(acc[mf][ng * 2 + 1], ah[mf], bh[2], bh[3]);
                mma16816(acc[mf][ng * 2 + 1], ah[mf], bl[2], bl[3]);
                mma16816(acc[mf][ng * 2 + 1], al[mf], bh[2], bh[3]);
            }
        }
    }
}

// loader: A planes from (ah_src, al_src) with row stride lda; B planes from (bh_src, bl_src)
// with row stride ldb (B tile is 32 rows x 128 cols starting at (kt*32, bcol0)).
__device__ __forceinline__ void load_tile(u16* base, int tid, int kt, int m0,
                                          const u16* ah_src, const u16* al_src, int lda,
                                          const u16* bh_src, const u16* bl_src, int ldb,
                                          int bcol0) {
    #pragma unroll
    for (int i = 0; i < 2; i++) {
        int lin = tid * 2 + i;
        int ar = lin >> 2, ac = lin & 3;
        int gr = m0 + ar;
        bool v = gr < N_SITES;
        int grc = v ? gr : 0;
        const u16* sh_ = ah_src + (size_t)grc * lda + kt * 32 + ac * 8;
        const u16* sl_ = al_src + (size_t)grc * lda + kt * 32 + ac * 8;
        cpa16(base + ar * 40 + ac * 8, sh_, v);
        cpa16(base + SM_ALO + ar * 40 + ac * 8, sl_, v);
        int br = lin >> 4, bc = lin & 15;
        const u16* bh_ = bh_src + (size_t)(kt * 32 + br) * ldb + bcol0 + bc * 8;
        const u16* bl_ = bl_src + (size_t)(kt * 32 + br) * ldb + bcol0 + bc * 8;
        cpa16(base + SM_BHI + br * 136 + bc * 8, bh_, true);
        cpa16(base + SM_BLO + br * 136 + bc * 8, bl_, true);
    }
    cpa_commit();
}

// ---------------- GEMM1: xln @ w1 -> +b1, GELU, store h planes, ssq ----------------
__global__ __launch_bounds__(256) void k_gemm1(const float* __restrict__ b1) {
    extern __shared__ u16 sm[];
    __shared__ float ssqs[128];
    int tid = threadIdx.x, lane = tid & 31, wid = tid >> 5;
    int mw = wid & 3, nw = wid >> 2;
    int nblk = blockIdx.x;           // 0..3 (fast dim -> L2 reuse of A)
    int m0 = blockIdx.y * 128;

    if (tid < 128) ssqs[tid] = 0.0f;

    float acc[2][8][4];
    #pragma unroll
    for (int i = 0; i < 2; i++)
        #pragma unroll
        for (int j = 0; j < 8; j++)
            #pragma unroll
            for (int r = 0; r < 4; r++) acc[i][j][r] = 0.f;

    load_tile(sm, tid, 0, m0, g_xh, g_xl, DIM, g_w1h, g_w1l, HID, nblk * 128);
    int stage = 0;
    #pragma unroll 1
    for (int kt = 0; kt < 4; kt++) {
        if (kt + 1 < 4) {
            load_tile(sm + (stage ^ 1) * SM_STAGE, tid, kt + 1, m0,
                      g_xh, g_xl, DIM, g_w1h, g_w1l, HID, nblk * 128);
            asm volatile("cp.async.wait_group 1;\n");
        } else {
            asm volatile("cp.async.wait_group 0;\n");
        }
        __syncthreads();
        mma_tile(sm + stage * SM_STAGE, lane, mw, nw, acc);
        __syncthreads();
        stage ^= 1;
    }

    // epilogue
    int colb = nw * 64 + (lane & 3) * 2;     // local col in 128-strip
    int colg = nblk * 128 + colb;            // global col
    float b1v[8][2];
    #pragma unroll
    for (int nf = 0; nf < 8; nf++) {
        b1v[nf][0] = b1[colg + nf * 8];
        b1v[nf][1] = b1[colg + nf * 8 + 1];
    }
    float ss[16];
    #pragma unroll
    for (int i = 0; i < 16; i++) ss[i] = 0.f;

    #pragma unroll
    for (int mf = 0; mf < 2; mf++) {
        #pragma unroll
        for (int half = 0; half < 2; half++) {
            int r = m0 + mw * 32 + mf * 16 + (lane >> 2) + half * 8;
            if (r >= N_SITES) continue;
            #pragma unroll
            for (int nf = 0; nf < 8; nf++) {
                float v0 = gelu_exact(acc[mf][nf][half * 2] + b1v[nf][0]);
                float v1 = gelu_exact(acc[mf][nf][half * 2 + 1] + b1v[nf][1]);
                ss[nf * 2] += v0 * v0;
                ss[nf * 2 + 1] += v1 * v1;
                u16 h0, l0, h1, l1;
                split_hl(v0, h0, l0);
                split_hl(v1, h1, l1);
                size_t off = (size_t)r * HID + colg + nf * 8;
                *(u32*)(g_hh + off) = (u32)h0 | ((u32)h1 << 16);
                *(u32*)(g_hl + off) = (u32)l0 | ((u32)l1 << 16);
            }
        }
    }
    __syncthreads();
    #pragma unroll
    for (int nf = 0; nf < 8; nf++) {
        atomicAdd(&ssqs[colb + nf * 8], ss[nf * 2]);
        atomicAdd(&ssqs[colb + nf * 8 + 1], ss[nf * 2 + 1]);
    }
    __syncthreads();
    if (tid < 128) atomicAdd(&g_ssq[nblk * 128 + tid], ssqs[tid]);
}

// ---------------- GRN scale ----------------
__global__ void k_grn(const float* __restrict__ grn_g) {
    __shared__ float sh[HID];
    int t = threadIdx.x;  // 512
    float gx = sqrtf(g_ssq[t]);
    sh[t] = gx;
    __syncthreads();
    for (int o = 256; o; o >>= 1) {
        if (t < o) sh[t] += sh[t + o];
        __syncthreads();
    }
    float nx = gx / (sh[0] * (1.0f / HID) + 1e-6f);
    g_scale[t] = 1.0f + grn_g[t] * nx;
}

// ---------------- GEMM2: (h*scale) @ w2 -> + c2 + residual ----------------
__global__ __launch_bounds__(256) void k_gemm2(const float* __restrict__ feats,
                                               float* __restrict__ out) {
    extern __shared__ u16 sm[];
    int tid = threadIdx.x, lane = tid & 31, wid = tid >> 5;
    int mw = wid & 3, nw = wid >> 2;
    int m0 = blockIdx.x * 128;

    float acc[2][8][4];
    #pragma unroll
    for (int i = 0; i < 2; i++)
        #pragma unroll
        for (int j = 0; j < 8; j++)
            #pragma unroll
            for (int r = 0; r < 4; r++) acc[i][j][r] = 0.f;

    load_tile(sm, tid, 0, m0, g_hh, g_hl, HID, g_w2h, g_w2l, DIM, 0);
    int stage = 0;
    #pragma unroll 1
    for (int kt = 0; kt < 16; kt++) {
        if (kt + 1 < 16) {
            load_tile(sm + (stage ^ 1) * SM_STAGE, tid, kt + 1, m0,
                      g_hh, g_hl, HID, g_w2h, g_w2l, DIM, 0);
            asm volatile("cp.async.wait_group 1;\n");
        } else {
            asm volatile("cp.async.wait_group 0;\n");
        }
        __syncthreads();
        mma_tile(sm + stage * SM_STAGE, lane, mw, nw, acc);
        __syncthreads();
        stage ^= 1;
    }

    int colb = nw * 64 + (lane & 3) * 2;
    float c2v[8][2];
    #pragma unroll
    for (int nf = 0; nf < 8; nf++) {
        c2v[nf][0] = g_c2[colb + nf * 8];
        c2v[nf][1] = g_c2[colb + nf * 8 + 1];
    }
    #pragma unroll
    for (int mf = 0; mf < 2; mf++) {
        #pragma unroll
        for (int half = 0; half < 2; half++) {
            int r = m0 + mw * 32 + mf * 16 + (lane >> 2) + half * 8;
            if (r >= N_SITES) continue;
            const float* frow = feats + (size_t)r * DIM;
            float* orow = out + (size_t)r * DIM;
            #pragma unroll
            for (int nf = 0; nf < 8; nf++) {
                float2 fv = *(const float2*)(frow + colb + nf * 8);
                float2 ov;
                ov.x = acc[mf][nf][half * 2] + c2v[nf][0] + fv.x;
                ov.y = acc[mf][nf][half * 2 + 1] + c2v[nf][1] + fv.y;
                *(float2*)(orow + colb + nf * 8) = ov;
            }
        }
    }
}

// ---------------- launch ----------------
extern "C" void kernel_launch(void* const* d_in, const int* in_sizes, int n_in,
                              void* d_out, int out_size) {
    const float* feats = (const float*)d_in[0];
    const int*   nidx  = (const int*)d_in[1];
    const float* dww   = (const float*)d_in[2];
    const float* dwb   = (const float*)d_in[3];
    const float* lng   = (const float*)d_in[4];
    const float* lnb   = (const float*)d_in[5];
    const float* w1    = (const float*)d_in[6];
    const float* b1    = (const float*)d_in[7];
    const float* grng  = (const float*)d_in[8];
    const float* grnb  = (const float*)d_in[9];
    const float* w2    = (const float*)d_in[10];
    const float* b2    = (const float*)d_in[11];
    float* out = (float*)d_out;

    cudaFuncSetAttribute(k_gemm1, cudaFuncAttributeMaxDynamicSharedMemorySize, SMEM_BYTES);
    cudaFuncSetAttribute(k_gemm2, cudaFuncAttributeMaxDynamicSharedMemorySize, SMEM_BYTES);

    k_init<<<1, 512>>>(grnb, w2, b2);
    k_w1prep<<<128, 512>>>(w1);
    k_dwln<<<(N_SITES * 32 + 255) / 256, 256>>>(feats, nidx, dww, dwb, lng, lnb);
    dim3 g1(4, (N_SITES + 127) / 128);
    k_gemm1<<<g1, 256, SMEM_BYTES>>>(b1);
    k_grn<<<1, 512>>>(grng);
    k_w2prep<<<128, 512>>>(w2);
    k_gemm2<<<(N_SITES + 127) / 128, 256, SMEM_BYTES>>>(feats, out);
}